// round 2
// baseline (speedup 1.0000x reference)
#include <cuda_runtime.h>
#include <stdint.h>

#define NROI   65536
#define NCASC  3
#define ROWLEN (NCASC * NROI)
#define NBATCH 64
#define TPB    1024
#define CAP    1024
#define TPOSC  0.99f
#define TNEGC  0.99f

static_assert(CAP == TPB, "bitonic path assumes CAP == TPB");

struct Keys { uint32_t k0[3]; uint32_t k1[3]; };

// ---------------------------------------------------------------------------
// JAX threefry2x32 (exact): rotations {13,15,26,6}/{17,29,16,24}, 5 injections
// ---------------------------------------------------------------------------
__host__ __device__ __forceinline__ void threefry2x32(
    uint32_t k0, uint32_t k1, uint32_t x0, uint32_t x1,
    uint32_t& o0, uint32_t& o1)
{
    uint32_t ks2 = k0 ^ k1 ^ 0x1BD11BDAu;
    x0 += k0; x1 += k1;
#define TFR(r) { x0 += x1; x1 = (x1 << (r)) | (x1 >> (32 - (r))); x1 ^= x0; }
    TFR(13) TFR(15) TFR(26) TFR(6)  x0 += k1;  x1 += ks2 + 1u;
    TFR(17) TFR(29) TFR(16) TFR(24) x0 += ks2; x1 += k0  + 2u;
    TFR(13) TFR(15) TFR(26) TFR(6)  x0 += k0;  x1 += k1  + 3u;
    TFR(17) TFR(29) TFR(16) TFR(24) x0 += k1;  x1 += ks2 + 4u;
    TFR(13) TFR(15) TFR(26) TFR(6)  x0 += ks2; x1 += k0  + 5u;
#undef TFR
    o0 = x0; o1 = x1;
}

// JAX partitionable random_bits(32) + uniform[0,1): bits = o0^o1 of tf(key, (0, idx))
__device__ __forceinline__ float u01(uint32_t k0, uint32_t k1, uint32_t idx)
{
    uint32_t a, c;
    threefry2x32(k0, k1, 0u, idx, a, c);
    uint32_t bits = a ^ c;
    return __uint_as_float((bits >> 9) | 0x3F800000u) - 1.0f;
}

__device__ const float c_POS_T[3] = {0.6f, 0.7f, 0.8f};
__device__ const float c_IOU_T[3] = {0.2f, 0.3f, 0.4f};
__device__ const float c_NEG_T[3] = {0.3f, 0.3f, 0.3f};

// ---------------------------------------------------------------------------
// Block helpers
// ---------------------------------------------------------------------------
__device__ __forceinline__ int block_reduce_sum_int(int v, int* sc)
{
    int tid = threadIdx.x;
    sc[tid] = v; __syncthreads();
    for (int s = TPB / 2; s > 0; s >>= 1) {
        if (tid < s) sc[tid] += sc[tid + s];
        __syncthreads();
    }
    int r = sc[0];
    __syncthreads();
    return r;
}

__device__ __forceinline__ float block_reduce_max(float v, float* sc)
{
    int tid = threadIdx.x;
    sc[tid] = v; __syncthreads();
    for (int s = TPB / 2; s > 0; s >>= 1) {
        if (tid < s) sc[tid] = fmaxf(sc[tid], sc[tid + s]);
        __syncthreads();
    }
    float r = sc[0];
    __syncthreads();
    return r;
}

// Descending bitonic sort of TPB floats in shared memory (caller synced).
__device__ void bitonic_desc(float* a)
{
    int tid = threadIdx.x;
    for (int k = 2; k <= TPB; k <<= 1) {
        for (int j = k >> 1; j > 0; j >>= 1) {
            int ixj = tid ^ j;
            if (ixj > tid) {
                float x = a[tid], y = a[ixj];
                bool desc = ((tid & k) == 0);
                if (desc ? (x < y) : (x > y)) { a[tid] = y; a[ixj] = x; }
            }
            __syncthreads();
        }
    }
}

// ---------------------------------------------------------------------------
// Exact fallbacks: kth-largest via binary search on float bit patterns.
// Never expected to run with these inputs, but guarantees correctness.
// ---------------------------------------------------------------------------
__device__ float kth_bs_iomask(int k, const float* ov, const float* io,
                               float POS_T, int nopos, float mx, int* sc)
{
    unsigned lo = 0u, hi = 0x7F800000u;  // [0, +inf)
    while (hi > lo) {
        unsigned mid = lo + ((hi - lo + 1u) >> 1);
        float t = __uint_as_float(mid);
        int c = 0;
        for (int j = threadIdx.x; j < NROI; j += TPB) {
            float o = ov[j], v = io[j];
            float im = nopos ? ((v >= mx) ? v : 0.0f)
                             : ((o >= POS_T) ? v : 0.0f);
            c += (im >= t);
        }
        c = block_reduce_sum_int(c, sc);
        if (c >= k) lo = mid; else hi = mid - 1u;
    }
    return __uint_as_float(lo);
}

__device__ float kth_bs_score(int k, const float* ov, float NEG_T,
                              uint32_t k0, uint32_t k1, uint32_t rng_base, int* sc)
{
    unsigned lo = 0u, hi = 0x7F800000u;
    while (hi > lo) {
        unsigned mid = lo + ((hi - lo + 1u) >> 1);
        float t = __uint_as_float(mid);
        int c = 0;
        for (int j = threadIdx.x; j < NROI; j += TPB) {
            float o = ov[j];
            if (o <= NEG_T) {
                float u = u01(k0, k1, rng_base + (uint32_t)j);
                c += (u >= t);
            }
        }
        c = block_reduce_sum_int(c, sc);
        if (c >= k) lo = mid; else hi = mid - 1u;
    }
    return __uint_as_float(lo);
}

// ---------------------------------------------------------------------------
// Main kernel: one block per (cascade h, batch b) row.
// ---------------------------------------------------------------------------
__global__ __launch_bounds__(TPB)
void label_cls_kernel(const float* __restrict__ g_ov,
                      const float* __restrict__ g_io,
                      const float* __restrict__ g_nm,
                      float* __restrict__ g_out,
                      Keys keys)
{
    __shared__ float s_sort[TPB];
    __shared__ float s_posv[CAP];
    __shared__ float s_negv[CAP];
    __shared__ int   s_negi[CAP];
    __shared__ int   s_cp, s_cn;

    const int tid = threadIdx.x;
    const int h = blockIdx.x >> 6;    // /64
    const int b = blockIdx.x & 63;

    const float POS_T = c_POS_T[h];
    const float NEG_T = c_NEG_T[h];
    const float IOU_T = c_IOU_T[h];
    const uint32_t k0 = keys.k0[h];
    const uint32_t k1 = keys.k1[h];
    const uint32_t rng_base = (uint32_t)b * (uint32_t)NROI;  // flat idx = b*NROI + j

    const size_t rowoff = (size_t)b * ROWLEN + (size_t)h * NROI;
    const float* ov = g_ov + rowoff;
    const float* io = g_io + rowoff;
    const float* nm = g_nm + rowoff;
    float*       out = g_out + rowoff;

    if (tid == 0) { s_cp = 0; s_cn = 0; }
    __syncthreads();

    // ---------------- Pass 1: reductions + candidate collection ----------------
    float lmax = 0.0f;
    int lpos = 0, lelig = 0;
    const float4* ov4 = (const float4*)ov;
    const float4* io4 = (const float4*)io;

    for (int q = tid; q < NROI / 4; q += TPB) {
        float4 o4 = ov4[q];
        float4 v4 = io4[q];
        int jb = q * 4;
#pragma unroll
        for (int l = 0; l < 4; l++) {
            float o = (&o4.x)[l];
            float v = (&v4.x)[l];
            lmax = fmaxf(lmax, v);
            bool pm = (o >= POS_T);
            lpos += pm;
            if (pm && v >= TPOSC) {
                int p = atomicAdd(&s_cp, 1);
                if (p < CAP) s_posv[p] = v;
            }
            bool el = (o <= NEG_T);
            lelig += el;
            if (el) {
                float u = u01(k0, k1, rng_base + (uint32_t)(jb + l));
                if (u >= TNEGC) {
                    int p = atomicAdd(&s_cn, 1);
                    if (p < CAP) { s_negv[p] = u; s_negi[p] = jb + l; }
                }
            }
        }
    }
    __syncthreads();

    float mx     = block_reduce_max(lmax, s_sort);
    int poscnt   = block_reduce_sum_int(lpos, (int*)s_sort);
    int eligcnt  = block_reduce_sum_int(lelig, (int*)s_sort);
    int cp = s_cp;
    int cn = s_cn;

    // ---------------- Positive threshold (16th + 2nd largest of iou_masked) ----
    int nopos = (poscnt == 0);
    float t16, top2 = 0.0f;
    if (!nopos && cp >= 16 && cp <= CAP) {
        s_sort[tid] = (tid < cp) ? s_posv[tid] : -1.0f;
        __syncthreads();
        bitonic_desc(s_sort);
        t16 = s_sort[15];
        top2 = s_sort[1];
        __syncthreads();
    } else {
        t16 = kth_bs_iomask(16, ov, io, POS_T, nopos, mx, (int*)s_sort);
        if (h == 0) top2 = kth_bs_iomask(2, ov, io, POS_T, nopos, mx, (int*)s_sort);
    }
    // tk = t16*(t16>=TH); tk += TH*(tk==0)  ==  (t16 >= TH) ? t16 : TH
    float tk = (t16 >= IOU_T) ? t16 : IOU_T;

    // ---------------- Negative threshold (48th largest random score) -----------
    float kth;
    int negfast;
    if (cn >= 48 && cn <= CAP) {
        negfast = 1;
        s_sort[tid] = (tid < cn) ? s_negv[tid] : -1.0f;
        __syncthreads();
        bitonic_desc(s_sort);
        kth = s_sort[47];
        __syncthreads();
    } else {
        negfast = 0;
        // kth = -inf when fewer than 48 eligible -> all eligible become neg.
        // u >= -1.0f is equivalent since u in [0,1).
        kth = (eligcnt < 48) ? -1.0f
            : kth_bs_score(48, ov, NEG_T, k0, k1, rng_base, (int*)s_sort);
    }

    // ---------------- Pass 2: write labels -------------------------------------
    const float4* nm4 = (const float4*)nm;
    float4* out4 = (float4*)out;
    for (int q = tid; q < NROI / 4; q += TPB) {
        float4 o4 = ov4[q];
        float4 v4 = io4[q];
        float4 m4 = nm4[q];
        float4 r;
        int jb = q * 4;
#pragma unroll
        for (int l = 0; l < 4; l++) {
            float o = (&o4.x)[l];
            float v = (&v4.x)[l];
            float nmv = (&m4.x)[l];
            float im = nopos ? ((v >= mx) ? v : 0.0f)
                             : ((o >= POS_T) ? v : 0.0f);
            float posb = (im >= tk) ? 1.0f : 0.0f;
            if (h == 0) {
                posb = ((posb > 0.0f) || (im > top2)) ? 1.0f : 0.0f;
            }
            float posf = posb * nmv;
            float negf = 0.0f;
            if (!negfast) {
                if (o <= NEG_T) {
                    float u = u01(k0, k1, rng_base + (uint32_t)(jb + l));
                    if (u >= kth) negf = 1.0f;
                }
            }
            (&r.x)[l] = (-1.0f + negf) + 2.0f * posf;
        }
        out4[q] = r;
    }

    // ---------------- Neg candidate overwrite (fast path) ----------------------
    if (negfast) {
        __syncthreads();  // order after pass-2 stores within the block
        for (int c = tid; c < cn; c += TPB) {
            if (s_negv[c] >= kth) {
                int j = s_negi[c];
                float o = ov[j], v = io[j], nmv = nm[j];
                float im = nopos ? ((v >= mx) ? v : 0.0f)
                                 : ((o >= POS_T) ? v : 0.0f);
                float posb = (im >= tk) ? 1.0f : 0.0f;
                if (h == 0) {
                    posb = ((posb > 0.0f) || (im > top2)) ? 1.0f : 0.0f;
                }
                float posf = posb * nmv;
                out[j] = (-1.0f + 1.0f) + 2.0f * posf;
            }
        }
    }
}

// ---------------------------------------------------------------------------
// Launch
// ---------------------------------------------------------------------------
extern "C" void kernel_launch(void* const* d_in, const int* in_sizes, int n_in,
                              void* d_out, int out_size)
{
    const float* ov = (const float*)d_in[0];
    const float* io = (const float*)d_in[1];
    const float* nm = (const float*)d_in[2];
    float* out = (float*)d_out;

    // keys[h] = threefry2x32(key(42)=(0,42), counts (0, h))  [partitionable split]
    Keys keys;
    for (int h = 0; h < NCASC; h++) {
        uint32_t a, c;
        threefry2x32(0u, 42u, 0u, (uint32_t)h, a, c);
        keys.k0[h] = a;
        keys.k1[h] = c;
    }

    label_cls_kernel<<<NBATCH * NCASC, TPB>>>(ov, io, nm, out, keys);
}

// round 3
// speedup vs baseline: 1.0244x; 1.0244x over previous
#include <cuda_runtime.h>
#include <stdint.h>

#define NROI    65536
#define NCASC   3
#define ROWLEN  (NCASC * NROI)
#define NBATCH  64
#define NROWS   (NBATCH * NCASC)
#define TPB     1024
#define CHUNK   8192                 // elements compacted per chunk
#define NCHUNK  (NROI / CHUNK)       // 8
#define Q_PER_CHUNK (CHUNK / 4)      // float4s per chunk = 2048
#define POSCAP  1024
#define NEGCAP  1024
#define SELCAP  64
#define TPOSC   0.99f
#define TNEGC   0.99f

#define MODE_LIST    0
#define MODE_ALLELIG 1
#define MODE_SLOW    2

struct Keys { uint32_t k0[3]; uint32_t k1[3]; };
struct RowPar { float mx, tk, top2, kth; int nopos, mode; };

__device__ RowPar g_par[NROWS];
__device__ int    g_selj[NROWS * SELCAP];
__device__ int    g_selcnt[NROWS];

__device__ const float c_POS_T[3] = {0.6f, 0.7f, 0.8f};
__device__ const float c_IOU_T[3] = {0.2f, 0.3f, 0.4f};
__device__ const float c_NEG_T[3] = {0.3f, 0.3f, 0.3f};

// ---------------------------------------------------------------------------
// JAX threefry2x32 (exact) + partitionable uniform
// ---------------------------------------------------------------------------
__host__ __device__ __forceinline__ void threefry2x32(
    uint32_t k0, uint32_t k1, uint32_t x0, uint32_t x1,
    uint32_t& o0, uint32_t& o1)
{
    uint32_t ks2 = k0 ^ k1 ^ 0x1BD11BDAu;
    x0 += k0; x1 += k1;
#define TFR(r) { x0 += x1; x1 = (x1 << (r)) | (x1 >> (32 - (r))); x1 ^= x0; }
    TFR(13) TFR(15) TFR(26) TFR(6)  x0 += k1;  x1 += ks2 + 1u;
    TFR(17) TFR(29) TFR(16) TFR(24) x0 += ks2; x1 += k0  + 2u;
    TFR(13) TFR(15) TFR(26) TFR(6)  x0 += k0;  x1 += k1  + 3u;
    TFR(17) TFR(29) TFR(16) TFR(24) x0 += k1;  x1 += ks2 + 4u;
    TFR(13) TFR(15) TFR(26) TFR(6)  x0 += ks2; x1 += k0  + 5u;
#undef TFR
    o0 = x0; o1 = x1;
}

__device__ __forceinline__ float u01(uint32_t k0, uint32_t k1, uint32_t idx)
{
    uint32_t a, c;
    threefry2x32(k0, k1, 0u, idx, a, c);
    uint32_t bits = a ^ c;
    return __uint_as_float((bits >> 9) | 0x3F800000u) - 1.0f;
}

// ---------------------------------------------------------------------------
// Block helpers (s_red is a 1024-entry scratch buffer)
// ---------------------------------------------------------------------------
__device__ __forceinline__ int block_reduce_sum_int(int v, int* sc)
{
    int tid = threadIdx.x;
    sc[tid] = v; __syncthreads();
    for (int s = TPB / 2; s > 0; s >>= 1) {
        if (tid < s) sc[tid] += sc[tid + s];
        __syncthreads();
    }
    int r = sc[0];
    __syncthreads();
    return r;
}

__device__ __forceinline__ float block_reduce_max(float v, float* sc)
{
    int tid = threadIdx.x;
    sc[tid] = v; __syncthreads();
    for (int s = TPB / 2; s > 0; s >>= 1) {
        if (tid < s) sc[tid] = fmaxf(sc[tid], sc[tid + s]);
        __syncthreads();
    }
    float r = sc[0];
    __syncthreads();
    return r;
}

__device__ void bitonic_desc(float* a)
{
    int tid = threadIdx.x;
    for (int k = 2; k <= TPB; k <<= 1) {
        for (int j = k >> 1; j > 0; j >>= 1) {
            int ixj = tid ^ j;
            if (ixj > tid) {
                float x = a[tid], y = a[ixj];
                bool desc = ((tid & k) == 0);
                if (desc ? (x < y) : (x > y)) { a[tid] = y; a[ixj] = x; }
            }
            __syncthreads();
        }
    }
}

// ---------------------------------------------------------------------------
// Exact fallbacks (never expected to run; guarantee correctness)
// ---------------------------------------------------------------------------
__device__ float kth_bs_iomask(int k, const float* ov, const float* io,
                               float POS_T, int nopos, float mx, int* sc)
{
    unsigned lo = 0u, hi = 0x7F800000u;
    while (hi > lo) {
        unsigned mid = lo + ((hi - lo + 1u) >> 1);
        float t = __uint_as_float(mid);
        int c = 0;
        for (int j = threadIdx.x; j < NROI; j += TPB) {
            float o = ov[j], v = io[j];
            float im = nopos ? ((v >= mx) ? v : 0.0f)
                             : ((o >= POS_T) ? v : 0.0f);
            c += (im >= t);
        }
        c = block_reduce_sum_int(c, sc);
        if (c >= k) lo = mid; else hi = mid - 1u;
    }
    return __uint_as_float(lo);
}

__device__ float kth_bs_score(int k, const float* ov, float NEG_T,
                              uint32_t k0, uint32_t k1, uint32_t rng_base, int* sc)
{
    unsigned lo = 0u, hi = 0x7F800000u;
    while (hi > lo) {
        unsigned mid = lo + ((hi - lo + 1u) >> 1);
        float t = __uint_as_float(mid);
        int c = 0;
        for (int j = threadIdx.x; j < NROI; j += TPB) {
            float o = ov[j];
            if (o <= NEG_T) {
                float u = u01(k0, k1, rng_base + (uint32_t)j);
                c += (u >= t);
            }
        }
        c = block_reduce_sum_int(c, sc);
        if (c >= k) lo = mid; else hi = mid - 1u;
    }
    return __uint_as_float(lo);
}

// ---------------------------------------------------------------------------
// Kernel A: per-row statistics. One block per row (r = b*3 + h, contiguous).
// Eligible indices are compacted to smem per chunk so threefry runs at
// full warp density (3.3x fewer warp-iterations than predicated).
// ---------------------------------------------------------------------------
__global__ __launch_bounds__(TPB)
void stats_kernel(const float* __restrict__ g_ov,
                  const float* __restrict__ g_io,
                  Keys keys)
{
    __shared__ uint16_t s_eidx[CHUNK];     // 16 KB: compacted eligible j (j < 65536)
    __shared__ float    s_red[TPB];        // 4 KB scratch (reduce / sort)
    __shared__ float    s_posv[POSCAP];    // 4 KB
    __shared__ float    s_negu[NEGCAP];    // 4 KB
    __shared__ int      s_negj[NEGCAP];    // 4 KB
    __shared__ int      s_cp, s_cn, s_ec, s_sel;

    const int tid = threadIdx.x;
    const int r = blockIdx.x;
    const int b = r / 3;
    const int h = r % 3;

    const float POS_T = c_POS_T[h];
    const float NEG_T = c_NEG_T[h];
    const float IOU_T = c_IOU_T[h];
    const uint32_t k0 = keys.k0[h];
    const uint32_t k1 = keys.k1[h];
    const uint32_t rng_base = (uint32_t)b * (uint32_t)NROI;

    const float* ov = g_ov + (size_t)r * NROI;
    const float* io = g_io + (size_t)r * NROI;
    const float4* ov4 = (const float4*)ov;
    const float4* io4 = (const float4*)io;

    if (tid == 0) { s_cp = 0; s_cn = 0; }

    float lmax = 0.0f;
    int lpos = 0, lelig = 0;
    const int lane = tid & 31;

    for (int c = 0; c < NCHUNK; c++) {
        __syncthreads();
        if (tid == 0) s_ec = 0;
        __syncthreads();

        // scan + compact eligible indices
#pragma unroll
        for (int it = 0; it < Q_PER_CHUNK / TPB; it++) {
            int q = c * Q_PER_CHUNK + it * TPB + tid;
            float4 o4 = ov4[q];
            float4 v4 = io4[q];
            int jb = q * 4;
#pragma unroll
            for (int l = 0; l < 4; l++) {
                float o = (&o4.x)[l];
                float v = (&v4.x)[l];
                lmax = fmaxf(lmax, v);
                bool pm = (o >= POS_T);
                lpos += pm;
                if (pm && v >= TPOSC) {
                    int p = atomicAdd(&s_cp, 1);
                    if (p < POSCAP) s_posv[p] = v;
                }
                bool el = (o <= NEG_T);
                lelig += el;
                unsigned m = __ballot_sync(0xFFFFFFFFu, el);
                if (el) {
                    int leader = __ffs(m) - 1;
                    int base = 0;
                    if (lane == leader) base = atomicAdd(&s_ec, __popc(m));
                    base = __shfl_sync(m, base, leader);
                    int off = base + __popc(m & ((1u << lane) - 1u));
                    s_eidx[off] = (uint16_t)(jb + l);
                }
            }
        }
        __syncthreads();

        // dense threefry over compacted eligible indices
        int nE = s_ec;
        for (int t = tid; t < nE; t += TPB) {
            int j = (int)s_eidx[t];
            float u = u01(k0, k1, rng_base + (uint32_t)j);
            if (u >= TNEGC) {
                int p = atomicAdd(&s_cn, 1);
                if (p < NEGCAP) { s_negu[p] = u; s_negj[p] = j; }
            }
        }
    }
    __syncthreads();

    float mx    = block_reduce_max(lmax, s_red);
    int poscnt  = block_reduce_sum_int(lpos, (int*)s_red);
    int eligcnt = block_reduce_sum_int(lelig, (int*)s_red);
    int cp = s_cp;
    int cn = s_cn;

    // -------- positive threshold: 16th (+2nd) largest of iou_masked --------
    int nopos = (poscnt == 0);
    float t16, top2 = 0.0f;
    if (!nopos && cp >= 16 && cp <= POSCAP) {
        s_red[tid] = (tid < cp) ? s_posv[tid] : -1.0f;
        __syncthreads();
        bitonic_desc(s_red);
        t16 = s_red[15];
        top2 = s_red[1];
        __syncthreads();
    } else {
        t16 = kth_bs_iomask(16, ov, io, POS_T, nopos, mx, (int*)s_red);
        if (h == 0) top2 = kth_bs_iomask(2, ov, io, POS_T, nopos, mx, (int*)s_red);
    }
    float tk = (t16 >= IOU_T) ? t16 : IOU_T;

    // -------- negative threshold: 48th largest random score among eligible ----
    float kth = -1.0f;
    int mode;
    int selcnt = 0;
    if (eligcnt < 48) {
        mode = MODE_ALLELIG;               // kth = -inf: all eligible are neg
    } else if (cn >= 48 && cn <= NEGCAP) {
        s_red[tid] = (tid < cn) ? s_negu[tid] : -1.0f;
        __syncthreads();
        bitonic_desc(s_red);
        kth = s_red[47];
        __syncthreads();
        if (tid == 0) s_sel = 0;
        __syncthreads();
        if (tid < cn && s_negu[tid] >= kth) {
            int p = atomicAdd(&s_sel, 1);
            if (p < SELCAP) g_selj[r * SELCAP + p] = s_negj[tid];
        }
        __syncthreads();
        selcnt = s_sel;
        if (selcnt > SELCAP) { mode = MODE_SLOW; selcnt = 0; }  // kth stays exact
        else mode = MODE_LIST;
    } else {
        mode = MODE_SLOW;
        kth = kth_bs_score(48, ov, NEG_T, k0, k1, rng_base, (int*)s_red);
    }

    if (tid == 0) {
        g_selcnt[r] = selcnt;
        RowPar p;
        p.mx = mx; p.tk = tk; p.top2 = top2; p.kth = kth;
        p.nopos = nopos; p.mode = mode;
        g_par[r] = p;
    }
}

// ---------------------------------------------------------------------------
// Kernel B: elementwise labels (neg deferred to kernel C in LIST mode).
// neg_mask is loaded only where pos fires (~16 scalar loads per row).
// ---------------------------------------------------------------------------
__global__ __launch_bounds__(256)
void label_kernel(const float* __restrict__ g_ov,
                  const float* __restrict__ g_io,
                  const float* __restrict__ g_nm,
                  float* __restrict__ g_out,
                  Keys keys)
{
    int gq = blockIdx.x * 256 + threadIdx.x;       // float4 index
    int r = gq >> 14;                              // 16384 float4 per row
    int h = r % 3;                                 // rows are (b*3 + h) contiguous

    RowPar p = g_par[r];
    const float POS_T = c_POS_T[h];
    const float NEG_T = c_NEG_T[h];

    float4 o4 = ((const float4*)g_ov)[gq];
    float4 v4 = ((const float4*)g_io)[gq];
    float4 res;

    int jb = (gq & 16383) * 4;
    uint32_t rng_base = (uint32_t)(r / 3) * (uint32_t)NROI;
    size_t ebase = (size_t)gq * 4;

#pragma unroll
    for (int l = 0; l < 4; l++) {
        float o = (&o4.x)[l];
        float v = (&v4.x)[l];
        float im = p.nopos ? ((v >= p.mx) ? v : 0.0f)
                           : ((o >= POS_T) ? v : 0.0f);
        bool posb = (im >= p.tk);
        if (h == 0) posb = posb || (im > p.top2);
        float posf = 0.0f;
        if (posb) posf = g_nm[ebase + l];          // rare scalar load

        float negf = 0.0f;
        if (p.mode == MODE_ALLELIG) {
            negf = (o <= NEG_T) ? 1.0f : 0.0f;
        } else if (p.mode == MODE_SLOW) {
            if (o <= NEG_T) {
                float u = u01(keys.k0[h], keys.k1[h],
                              rng_base + (uint32_t)(jb + l));
                if (u >= p.kth) negf = 1.0f;
            }
        }
        (&res.x)[l] = (-1.0f + negf) + 2.0f * posf;
    }
    ((float4*)g_out)[gq] = res;
}

// ---------------------------------------------------------------------------
// Kernel C: scatter-overwrite the selected negatives (LIST mode only).
// ---------------------------------------------------------------------------
__global__ void scatter_kernel(const float* __restrict__ g_ov,
                               const float* __restrict__ g_io,
                               const float* __restrict__ g_nm,
                               float* __restrict__ g_out)
{
    int r = blockIdx.x;
    int h = r % 3;
    RowPar p = g_par[r];
    int cnt = g_selcnt[r];
    const float POS_T = c_POS_T[h];
    size_t rowoff = (size_t)r * NROI;

    for (int i = threadIdx.x; i < cnt; i += blockDim.x) {
        int j = g_selj[r * SELCAP + i];
        float o = g_ov[rowoff + j];
        float v = g_io[rowoff + j];
        float im = p.nopos ? ((v >= p.mx) ? v : 0.0f)
                           : ((o >= POS_T) ? v : 0.0f);
        bool posb = (im >= p.tk);
        if (h == 0) posb = posb || (im > p.top2);
        float posf = 0.0f;
        if (posb) posf = g_nm[rowoff + j];
        g_out[rowoff + j] = 2.0f * posf;           // -1 + 1 + 2*pos
    }
}

// ---------------------------------------------------------------------------
// Launch
// ---------------------------------------------------------------------------
extern "C" void kernel_launch(void* const* d_in, const int* in_sizes, int n_in,
                              void* d_out, int out_size)
{
    const float* ov = (const float*)d_in[0];
    const float* io = (const float*)d_in[1];
    const float* nm = (const float*)d_in[2];
    float* out = (float*)d_out;

    Keys keys;
    for (int h = 0; h < NCASC; h++) {
        uint32_t a, c;
        threefry2x32(0u, 42u, 0u, (uint32_t)h, a, c);
        keys.k0[h] = a;
        keys.k1[h] = c;
    }

    stats_kernel<<<NROWS, TPB>>>(ov, io, keys);
    label_kernel<<<(NROWS * (NROI / 4)) / 256, 256>>>(ov, io, nm, out, keys);
    scatter_kernel<<<NROWS, 64>>>(ov, io, nm, out);
}